// round 5
// baseline (speedup 1.0000x reference)
#include <cuda_runtime.h>
#include <cstdint>
#include <algorithm>

// ---------------------------------------------------------------------------
// Problem constants
// ---------------------------------------------------------------------------
#define BATCH   256
#define FDIM    128
#define EDIM    128
#define DDIM    64
#define MAXDEG  64
#define NN1     25
#define NN0     10
#define ROWS1   (BATCH * 2 * NN1)     // 12800 per set
#define ROWS2   (ROWS1 * 2 * NN0)     // 256000 per set
#define ROWS_BIG (2 * ROWS1)          // 25600
#define KDIM    384

#define RPB     64                    // rows per block in fused_l0
#define ASTRIDE 388                   // 384 + 4 pad -> conflict-free A-frag LDS
#define SM_A    (RPB * ASTRIDE)       // 24832 floats
#define BSZ     (8 * 128)             // one hi (or lo) 8-k panel
#define SM_B    (2 * 2 * BSZ)         // double-buffered hi+lo panels = 4096 floats
#define SMEM_FUSED ((SM_A + SM_B) * 4)   // 115712 B

// ---------------------------------------------------------------------------
// Static device scratch
// ---------------------------------------------------------------------------
__device__ int   g_lvl1[2][ROWS1];
__device__ int   g_lvl2[2][ROWS2];
__device__ float g_h11[(size_t)ROWS_BIG * EDIM];      // 13.1 MB
__device__ float g_agg0[2 * BATCH * KDIM];
__device__ float g_h10[2 * BATCH * EDIM];
__device__ float g_aggL1[2 * BATCH * KDIM];
__device__ float g_hhead3[3][2 * BATCH * EDIM];
__device__ float g_Whi[KDIM * EDIM];
__device__ float g_Wlo[KDIM * EDIM];

struct ColsAll {
    int out0[2][NN1];
    int in0[2][NN1];
    int out1[2][NN0];
    int in1[2][NN0];
};

// ---------------------------------------------------------------------------
// Helpers
// ---------------------------------------------------------------------------
__device__ __forceinline__ float sigmoidf_stable(float x) {
    if (x >= 0.f) {
        return 1.f / (1.f + expf(-x));
    } else {
        float e = expf(x);
        return e / (1.f + e);
    }
}

__device__ __forceinline__ unsigned tf32_rna(float x) {
    unsigned r;
    asm("cvt.rna.tf32.f32 %0, %1;" : "=r"(r) : "f"(x));
    return r;
}

__device__ __forceinline__ void mma_tf32(float* c,
                                         unsigned a0, unsigned a1,
                                         unsigned a2, unsigned a3,
                                         unsigned b0, unsigned b1) {
    asm volatile(
        "mma.sync.aligned.m16n8k8.row.col.f32.tf32.tf32.f32 "
        "{%0,%1,%2,%3}, {%4,%5,%6,%7}, {%8,%9}, {%0,%1,%2,%3};"
        : "+f"(c[0]), "+f"(c[1]), "+f"(c[2]), "+f"(c[3])
        : "r"(a0), "r"(a1), "r"(a2), "r"(a3), "r"(b0), "r"(b1));
}

// ---------------------------------------------------------------------------
// Sampling index kernels
// ---------------------------------------------------------------------------
__global__ void build_lvl1(const int* __restrict__ nodes1,
                           const int* __restrict__ nodes2,
                           const int* __restrict__ nbr_out,
                           const int* __restrict__ nbr_in,
                           ColsAll cols) {
    int tid = blockIdx.x * blockDim.x + threadIdx.x;
    const int total = 2 * ROWS1;
    if (tid >= total) return;
    int set = tid / ROWS1;
    int rem = tid - set * ROWS1;
    int i = rem / (2 * NN1);
    int j = rem - i * (2 * NN1);
    int node = (set ? nodes2 : nodes1)[i];
    int col;
    const int* nbr;
    if (j < NN1) { col = cols.out0[set][j];        nbr = nbr_out; }
    else         { col = cols.in0[set][j - NN1];   nbr = nbr_in;  }
    g_lvl1[set][rem] = nbr[(size_t)node * MAXDEG + col];
}

__global__ void build_lvl2(const int* __restrict__ nbr_out,
                           const int* __restrict__ nbr_in,
                           ColsAll cols) {
    int tid = blockIdx.x * blockDim.x + threadIdx.x;
    const int total = 2 * ROWS2;
    if (tid >= total) return;
    int set = tid / ROWS2;
    int rem = tid - set * ROWS2;
    int r = rem / (2 * NN0);
    int j = rem - r * (2 * NN0);
    int parent = g_lvl1[set][r];
    int col;
    const int* nbr;
    if (j < NN0) { col = cols.out1[set][j];        nbr = nbr_out; }
    else         { col = cols.in1[set][j - NN0];   nbr = nbr_in;  }
    g_lvl2[set][rem] = nbr[(size_t)parent * MAXDEG + col];
}

// Pre-split W_in into tf32 hi/lo (removes cvts from fused_l0 hot loop)
__global__ void prep_w(const float* __restrict__ W) {
    int idx = blockIdx.x * blockDim.x + threadIdx.x;   // 49152 total
    float w = W[idx];
    unsigned h = tf32_rna(w);
    float fh = __uint_as_float(h);
    g_Whi[idx] = fh;
    g_Wlo[idx] = __uint_as_float(tf32_rna(w - fh));
}

// ---------------------------------------------------------------------------
// Fused level-0 big path: gather+mean -> smem A[64][388], then
// sigmoid(A @ W_in) via 3xTF32 MMA -> g_h11.  Grid 400, block 256.
// ---------------------------------------------------------------------------
__global__ void __launch_bounds__(256, 2)
fused_l0(const float* __restrict__ feat) {
    extern __shared__ float sm[];
    float* As = sm;                 // [RPB][ASTRIDE]
    float* Bs = sm + SM_A;          // [2 buf][2 hi/lo][8][128] swizzled

    const int t    = threadIdx.x;
    const int lane = t & 31;
    const int w    = t >> 5;
    const int r0   = blockIdx.x * RPB;

    // ---- Phase 1: gather + mean into smem ----
    const float4* feat4 = reinterpret_cast<const float4*>(feat);
    const float inv = 1.0f / (float)NN0;
#pragma unroll
    for (int rr = 0; rr < RPB / 8; rr++) {
        int r = w * (RPB / 8) + rr;
        int R = r0 + r;
        int set = (R >= ROWS1) ? 1 : 0;
        int i = R - set * ROWS1;
        int self = g_lvl1[set][i];
        const int* l2 = &g_lvl2[set][i * 2 * NN0];

        float4 vs = feat4[(size_t)self * 32 + lane];
        float4 ao = make_float4(0.f, 0.f, 0.f, 0.f);
        float4 ai = make_float4(0.f, 0.f, 0.f, 0.f);
#pragma unroll
        for (int j = 0; j < NN0; j++) {
            float4 v = feat4[(size_t)l2[j] * 32 + lane];
            ao.x += v.x; ao.y += v.y; ao.z += v.z; ao.w += v.w;
        }
#pragma unroll
        for (int j = NN0; j < 2 * NN0; j++) {
            float4 v = feat4[(size_t)l2[j] * 32 + lane];
            ai.x += v.x; ai.y += v.y; ai.z += v.z; ai.w += v.w;
        }
        float* arow = &As[r * ASTRIDE];
        *reinterpret_cast<float4*>(&arow[lane * 4]) = vs;
        float4 mo = make_float4(ao.x * inv, ao.y * inv, ao.z * inv, ao.w * inv);
        float4 mi = make_float4(ai.x * inv, ai.y * inv, ai.z * inv, ai.w * inv);
        *reinterpret_cast<float4*>(&arow[128 + lane * 4]) = mo;
        *reinterpret_cast<float4*>(&arow[256 + lane * 4]) = mi;
    }

    // ---- Phase 2: 3xTF32 MMA with double-buffered pre-split W panels ----
    const int group = lane >> 2;
    const int tid4  = lane & 3;
    const int R0w   = (w & 3) * 16;
    const int C0    = (w >> 2) * 64;

    float acc[8][4];
#pragma unroll
    for (int j = 0; j < 8; j++)
#pragma unroll
        for (int q = 0; q < 4; q++) acc[j][q] = 0.f;

    const int pk = t >> 5;
    const int pn = (t & 31) * 4;
    const int sb = pk * 128 + (pn ^ (pk * 8));

    float4 whi = *reinterpret_cast<const float4*>(&g_Whi[pk * EDIM + pn]);
    float4 wlo = *reinterpret_cast<const float4*>(&g_Wlo[pk * EDIM + pn]);
    __syncthreads();   // As complete

    // stage panel 0 into buf 0, prefetch panel 1
    *reinterpret_cast<float4*>(&Bs[sb])       = whi;
    *reinterpret_cast<float4*>(&Bs[BSZ + sb]) = wlo;
    whi = *reinterpret_cast<const float4*>(&g_Whi[(8 + pk) * EDIM + pn]);
    wlo = *reinterpret_cast<const float4*>(&g_Wlo[(8 + pk) * EDIM + pn]);
    __syncthreads();   // buf 0 visible

    const int NP = KDIM / 8;   // 48
    for (int p = 0; p < NP; p++) {
        const float* buf = &Bs[(p & 1) * 2 * BSZ];

        // A fragment (m16 x k8)
        const float* ar  = &As[(R0w + group) * ASTRIDE + p * 8];
        const float* ar8 = ar + 8 * ASTRIDE;
        float x00 = ar[tid4];
        float x10 = ar8[tid4];
        float x01 = ar[tid4 + 4];
        float x11 = ar8[tid4 + 4];
        unsigned ah0 = tf32_rna(x00), ah1 = tf32_rna(x10),
                 ah2 = tf32_rna(x01), ah3 = tf32_rna(x11);
        unsigned al0 = tf32_rna(x00 - __uint_as_float(ah0));
        unsigned al1 = tf32_rna(x10 - __uint_as_float(ah1));
        unsigned al2 = tf32_rna(x01 - __uint_as_float(ah2));
        unsigned al3 = tf32_rna(x11 - __uint_as_float(ah3));

#pragma unroll
        for (int j = 0; j < 8; j++) {
            int nl = C0 + j * 8 + group;
            unsigned bh0 = __float_as_uint(buf[tid4 * 128 + (nl ^ (tid4 * 8))]);
            unsigned bh1 = __float_as_uint(
                buf[(tid4 + 4) * 128 + (nl ^ ((tid4 + 4) * 8))]);
            unsigned bl0 = __float_as_uint(buf[BSZ + tid4 * 128 + (nl ^ (tid4 * 8))]);
            unsigned bl1 = __float_as_uint(
                buf[BSZ + (tid4 + 4) * 128 + (nl ^ ((tid4 + 4) * 8))]);
            mma_tf32(acc[j], ah0, ah1, ah2, ah3, bh0, bh1);
            mma_tf32(acc[j], al0, al1, al2, al3, bh0, bh1);
            mma_tf32(acc[j], ah0, ah1, ah2, ah3, bl0, bl1);
        }

        if (p + 1 < NP) {
            float* nb = &Bs[((p + 1) & 1) * 2 * BSZ];
            *reinterpret_cast<float4*>(&nb[sb])       = whi;
            *reinterpret_cast<float4*>(&nb[BSZ + sb]) = wlo;
            if (p + 2 < NP) {
                whi = *reinterpret_cast<const float4*>(
                    &g_Whi[((p + 2) * 8 + pk) * EDIM + pn]);
                wlo = *reinterpret_cast<const float4*>(
                    &g_Wlo[((p + 2) * 8 + pk) * EDIM + pn]);
            }
        }
        __syncthreads();
    }

    // ---- Epilogue: sigmoid + store ----
    const int Ra = r0 + R0w + group;
    const int Rb = Ra + 8;
#pragma unroll
    for (int j = 0; j < 8; j++) {
        int col = C0 + j * 8 + 2 * tid4;
        float2 oa, ob;
        oa.x = sigmoidf_stable(acc[j][0]);
        oa.y = sigmoidf_stable(acc[j][1]);
        ob.x = sigmoidf_stable(acc[j][2]);
        ob.y = sigmoidf_stable(acc[j][3]);
        *reinterpret_cast<float2*>(&g_h11[(size_t)Ra * EDIM + col]) = oa;
        *reinterpret_cast<float2*>(&g_h11[(size_t)Rb * EDIM + col]) = ob;
    }
}

// ---------------------------------------------------------------------------
// Small path kernels (512 rows), warp-per-row float4
// ---------------------------------------------------------------------------
__global__ void agg_hop0(const float* __restrict__ feat,
                         const int* __restrict__ nodes1,
                         const int* __restrict__ nodes2) {
    int t = threadIdx.x, lane = t & 31, w = t >> 5;
    int r = blockIdx.x * 8 + w;          // 0..511
    int set = r >> 8, i = r & 255;
    int self = (set ? nodes2 : nodes1)[i];
    const int* l1 = &g_lvl1[set][i * 2 * NN1];
    const float4* feat4 = reinterpret_cast<const float4*>(feat);
    const float inv = 1.0f / (float)NN1;

    float4 vs = feat4[(size_t)self * 32 + lane];
    float4 ao = make_float4(0.f, 0.f, 0.f, 0.f);
    float4 ai = make_float4(0.f, 0.f, 0.f, 0.f);
#pragma unroll
    for (int j = 0; j < NN1; j++) {
        float4 v = feat4[(size_t)l1[j] * 32 + lane];
        ao.x += v.x; ao.y += v.y; ao.z += v.z; ao.w += v.w;
    }
#pragma unroll
    for (int j = NN1; j < 2 * NN1; j++) {
        float4 v = feat4[(size_t)l1[j] * 32 + lane];
        ai.x += v.x; ai.y += v.y; ai.z += v.z; ai.w += v.w;
    }
    float* a = &g_agg0[(size_t)r * KDIM];
    *reinterpret_cast<float4*>(&a[lane * 4]) = vs;
    *reinterpret_cast<float4*>(&a[128 + lane * 4]) =
        make_float4(ao.x * inv, ao.y * inv, ao.z * inv, ao.w * inv);
    *reinterpret_cast<float4*>(&a[256 + lane * 4]) =
        make_float4(ai.x * inv, ai.y * inv, ai.z * inv, ai.w * inv);
}

__global__ void agg_l1() {
    int t = threadIdx.x, lane = t & 31, w = t >> 5;
    int r = blockIdx.x * 8 + w;          // 0..511
    int set = r >> 8, i = r & 255;
    const float4* h4 = reinterpret_cast<const float4*>(
        &g_h11[(size_t)(set * ROWS1 + i * 2 * NN1) * EDIM]);
    const float inv = 1.0f / (float)NN1;

    float4 ao = make_float4(0.f, 0.f, 0.f, 0.f);
    float4 ai = make_float4(0.f, 0.f, 0.f, 0.f);
#pragma unroll
    for (int j = 0; j < NN1; j++) {
        float4 v = h4[(size_t)j * 32 + lane];
        ao.x += v.x; ao.y += v.y; ao.z += v.z; ao.w += v.w;
    }
#pragma unroll
    for (int j = NN1; j < 2 * NN1; j++) {
        float4 v = h4[(size_t)j * 32 + lane];
        ai.x += v.x; ai.y += v.y; ai.z += v.z; ai.w += v.w;
    }
    float4 vs = reinterpret_cast<const float4*>(&g_h10[(size_t)r * EDIM])[lane];
    float* a = &g_aggL1[(size_t)r * KDIM];
    *reinterpret_cast<float4*>(&a[lane * 4]) = vs;
    *reinterpret_cast<float4*>(&a[128 + lane * 4]) =
        make_float4(ao.x * inv, ao.y * inv, ao.z * inv, ao.w * inv);
    *reinterpret_cast<float4*>(&a[256 + lane * 4]) =
        make_float4(ai.x * inv, ai.y * inv, ai.z * inv, ai.w * inv);
}

// Generic small GEMM+sigmoid: C[M,128] = sigmoid(A[M,384] @ W[384,128])
__global__ void __launch_bounds__(256)
gemm_sig(const float* __restrict__ W0, const float* __restrict__ W1,
         const float* __restrict__ W2, int mode) {
    const float* A = (mode == 1) ? g_agg0 : g_aggL1;
    const float* W = (mode == 1) ? W0
                   : (blockIdx.y == 0 ? W0 : (blockIdx.y == 1 ? W1 : W2));
    float* C = (mode == 1) ? g_h10 : g_hhead3[blockIdx.y];

    __shared__ float As[16][128];
    __shared__ float Bs[16][128];

    int t  = threadIdx.x;
    int tx = t & 15;
    int ty = t >> 4;
    int m0 = blockIdx.x * 128;

    float acc[8][8];
#pragma unroll
    for (int i = 0; i < 8; i++)
#pragma unroll
        for (int j = 0; j < 8; j++) acc[i][j] = 0.f;

    for (int k0 = 0; k0 < KDIM; k0 += 16) {
#pragma unroll
        for (int l = 0; l < 2; l++) {
            int f4 = t * 2 + l;
            int m  = f4 >> 2;
            int kq = (f4 & 3) * 4;
            float4 v = *reinterpret_cast<const float4*>(
                &A[(size_t)(m0 + m) * KDIM + k0 + kq]);
            As[kq + 0][m] = v.x;
            As[kq + 1][m] = v.y;
            As[kq + 2][m] = v.z;
            As[kq + 3][m] = v.w;
        }
#pragma unroll
        for (int l = 0; l < 2; l++) {
            int f4 = t * 2 + l;
            int k  = f4 >> 5;
            int c  = (f4 & 31) * 4;
            *reinterpret_cast<float4*>(&Bs[k][c]) =
                *reinterpret_cast<const float4*>(&W[(size_t)(k0 + k) * EDIM + c]);
        }
        __syncthreads();
#pragma unroll
        for (int k = 0; k < 16; k++) {
            float4 a0 = *reinterpret_cast<const float4*>(&As[k][ty * 8]);
            float4 a1 = *reinterpret_cast<const float4*>(&As[k][ty * 8 + 4]);
            float4 b0 = *reinterpret_cast<const float4*>(&Bs[k][tx * 8]);
            float4 b1 = *reinterpret_cast<const float4*>(&Bs[k][tx * 8 + 4]);
            float a[8] = {a0.x, a0.y, a0.z, a0.w, a1.x, a1.y, a1.z, a1.w};
            float b[8] = {b0.x, b0.y, b0.z, b0.w, b1.x, b1.y, b1.z, b1.w};
#pragma unroll
            for (int i = 0; i < 8; i++)
#pragma unroll
                for (int j = 0; j < 8; j++) acc[i][j] += a[i] * b[j];
        }
        __syncthreads();
    }

#pragma unroll
    for (int i = 0; i < 8; i++) {
        int row = m0 + ty * 8 + i;
#pragma unroll
        for (int j = 0; j < 8; j++) {
            C[(size_t)row * EDIM + tx * 8 + j] = sigmoidf_stable(acc[i][j]);
        }
    }
}

// z[512,64] = g_hhead3[head] @ Wd; scatter into stacked output. grid (512, 3)
__global__ void proj3(const float* __restrict__ Wdm,
                      const float* __restrict__ Wds,
                      const float* __restrict__ Wdp,
                      float* __restrict__ out) {
    __shared__ float h[128];
    int head = blockIdx.y;
    const float* Wd = (head == 0) ? Wdm : (head == 1) ? Wds : Wdp;
    int r = blockIdx.x;
    int c = threadIdx.x;
    const float* H = g_hhead3[head];
    h[c]      = H[(size_t)r * EDIM + c];
    h[c + 64] = H[(size_t)r * EDIM + 64 + c];
    __syncthreads();
    float s = 0.f;
#pragma unroll
    for (int k = 0; k < 128; k++) s += h[k] * Wd[k * DDIM + c];
    int set = r >> 8;
    int i = r & 255;
    out[((size_t)(set * 3 + head) * BATCH + i) * DDIM + c] = s;
}

// ---------------------------------------------------------------------------
// Host-side JAX threefry reproduction (partitionable mode)
// ---------------------------------------------------------------------------
namespace tfry {

static inline uint32_t rotl32(uint32_t x, int d) { return (x << d) | (x >> (32 - d)); }

struct Key { uint32_t a, b; };

static Key threefry2x32(Key k, uint32_t x0, uint32_t x1) {
    uint32_t ks0 = k.a, ks1 = k.b, ks2 = k.a ^ k.b ^ 0x1BD11BDAu;
    x0 += ks0; x1 += ks1;
    static const int R0[4] = {13, 15, 26, 6};
    static const int R1[4] = {17, 29, 16, 24};
    auto rounds4 = [&](const int* R) {
        for (int i = 0; i < 4; i++) { x0 += x1; x1 = rotl32(x1, R[i]); x1 ^= x0; }
    };
    rounds4(R0); x0 += ks1; x1 += ks2 + 1u;
    rounds4(R1); x0 += ks2; x1 += ks0 + 2u;
    rounds4(R0); x0 += ks0; x1 += ks1 + 3u;
    rounds4(R1); x0 += ks1; x1 += ks2 + 4u;
    rounds4(R0); x0 += ks2; x1 += ks0 + 5u;
    return Key{x0, x1};
}

static Key fold(Key k, uint32_t i) { return threefry2x32(k, 0u, i); }

static void perm64_prefix(Key key, int n, int* out) {
    Key subkey = fold(key, 1);
    uint32_t bits[64];
    int idx[64];
    for (int i = 0; i < 64; i++) {
        Key r = threefry2x32(subkey, 0u, (uint32_t)i);
        bits[i] = r.a ^ r.b;
        idx[i] = i;
    }
    std::stable_sort(idx, idx + 64,
                     [&](int x, int y) { return bits[x] < bits[y]; });
    for (int j = 0; j < n; j++) out[j] = idx[j];
}

}  // namespace tfry

// ---------------------------------------------------------------------------
// kernel_launch
// ---------------------------------------------------------------------------
extern "C" void kernel_launch(void* const* d_in, const int* in_sizes, int n_in,
                              void* d_out, int out_size) {
    const int*   nodes1  = (const int*)d_in[0];
    const int*   nodes2  = (const int*)d_in[1];
    const int*   nbr_out = (const int*)d_in[2];
    const int*   nbr_in  = (const int*)d_in[3];
    const float* feat    = (const float*)d_in[4];
    const float* W_in    = (const float*)d_in[5];
    const float* W_mean  = (const float*)d_in[6];
    const float* W_std   = (const float*)d_in[7];
    const float* W_pi    = (const float*)d_in[8];
    const float* Wd_mean = (const float*)d_in[11];
    const float* Wd_std  = (const float*)d_in[12];
    const float* Wd_pi   = (const float*)d_in[13];
    float* out = (float*)d_out;

    cudaFuncSetAttribute(fused_l0, cudaFuncAttributeMaxDynamicSharedMemorySize,
                         SMEM_FUSED);

    // --- host threefry: sampling column indices ---
    ColsAll cols;
    tfry::Key root{0u, 42u};
    tfry::Key kset[2] = {tfry::fold(root, 0), tfry::fold(root, 1)};
    for (int set = 0; set < 2; set++) {
        tfry::Key key = kset[set];
        {
            tfry::Key nk = tfry::fold(key, 0);
            tfry::Key p1 = tfry::fold(key, 1);
            tfry::Key p2 = tfry::fold(key, 2);
            tfry::perm64_prefix(p1, NN1, cols.out0[set]);
            tfry::perm64_prefix(p2, NN1, cols.in0[set]);
            key = nk;
        }
        {
            tfry::Key p1 = tfry::fold(key, 1);
            tfry::Key p2 = tfry::fold(key, 2);
            tfry::perm64_prefix(p1, NN0, cols.out1[set]);
            tfry::perm64_prefix(p2, NN0, cols.in1[set]);
        }
    }

    // --- pipeline (fused_l0 deliberately at launch slot #4 for ncu capture) ---
    build_lvl1<<<(2 * ROWS1 + 255) / 256, 256>>>(nodes1, nodes2, nbr_out, nbr_in, cols);  // #1
    build_lvl2<<<(2 * ROWS2 + 255) / 256, 256>>>(nbr_out, nbr_in, cols);                  // #2
    prep_w<<<KDIM * EDIM / 256, 256>>>(W_in);                                             // #3
    fused_l0<<<ROWS_BIG / RPB, 256, SMEM_FUSED>>>(feat);                                  // #4 -> g_h11

    agg_hop0<<<64, 256>>>(feat, nodes1, nodes2);                                          // #5
    gemm_sig<<<dim3((2 * BATCH) / 128, 1), 256>>>(W_in, nullptr, nullptr, 1);             // #6 -> g_h10
    agg_l1<<<64, 256>>>();                                                                // #7 -> g_aggL1
    gemm_sig<<<dim3((2 * BATCH) / 128, 3), 256>>>(W_mean, W_std, W_pi, 2);                // #8 -> g_hhead3
    proj3<<<dim3(2 * BATCH, 3), 64>>>(Wd_mean, Wd_std, Wd_pi, out);                       // #9
}

// round 6
// speedup vs baseline: 1.3178x; 1.3178x over previous
#include <cuda_runtime.h>
#include <cstdint>
#include <algorithm>

// ---------------------------------------------------------------------------
// Problem constants
// ---------------------------------------------------------------------------
#define BATCH   256
#define FDIM    128
#define EDIM    128
#define DDIM    64
#define MAXDEG  64
#define NN1     25
#define NN0     10
#define ROWS1   (BATCH * 2 * NN1)     // 12800 per set
#define ROWS2   (ROWS1 * 2 * NN0)     // 256000 per set
#define ROWS_BIG (2 * ROWS1)          // 25600
#define KDIM    384

#define RPB     64                    // rows per block in fused_l0
#define ASTRIDE 388                   // 384 + 4 pad -> conflict-free A-frag LDS
#define SM_A    (RPB * ASTRIDE)       // 24832 floats
#define BSZ     (8 * 128)             // one hi (or lo) 8-k panel
#define SM_B    (2 * BSZ)             // hi+lo panel (single-buffered) = 2048 floats
#define SMEM_FUSED ((SM_A + SM_B) * 4)   // 107520 B  (2 blocks/SM fits 228KB)

// ---------------------------------------------------------------------------
// Static device scratch
// ---------------------------------------------------------------------------
__device__ int   g_lvl1[2][ROWS1];
__device__ int   g_lvl2[2][ROWS2];
__device__ float g_h11[(size_t)ROWS_BIG * EDIM];      // 13.1 MB
__device__ float g_agg0[2 * BATCH * KDIM];
__device__ float g_h10[2 * BATCH * EDIM];
__device__ float g_aggL1[2 * BATCH * KDIM];
__device__ float g_hhead3[3][2 * BATCH * EDIM];
__device__ float g_Whi[KDIM * EDIM];
__device__ float g_Wlo[KDIM * EDIM];

struct ColsAll {
    int out0[2][NN1];
    int in0[2][NN1];
    int out1[2][NN0];
    int in1[2][NN0];
};

// ---------------------------------------------------------------------------
// Helpers
// ---------------------------------------------------------------------------
__device__ __forceinline__ float sigmoidf_stable(float x) {
    if (x >= 0.f) {
        return 1.f / (1.f + expf(-x));
    } else {
        float e = expf(x);
        return e / (1.f + e);
    }
}

__device__ __forceinline__ unsigned tf32_rna(float x) {
    unsigned r;
    asm("cvt.rna.tf32.f32 %0, %1;" : "=r"(r) : "f"(x));
    return r;
}

__device__ __forceinline__ void mma_tf32(float* c,
                                         unsigned a0, unsigned a1,
                                         unsigned a2, unsigned a3,
                                         unsigned b0, unsigned b1) {
    asm volatile(
        "mma.sync.aligned.m16n8k8.row.col.f32.tf32.tf32.f32 "
        "{%0,%1,%2,%3}, {%4,%5,%6,%7}, {%8,%9}, {%0,%1,%2,%3};"
        : "+f"(c[0]), "+f"(c[1]), "+f"(c[2]), "+f"(c[3])
        : "r"(a0), "r"(a1), "r"(a2), "r"(a3), "r"(b0), "r"(b1));
}

// ---------------------------------------------------------------------------
// Sampling index kernels
// ---------------------------------------------------------------------------
__global__ void build_lvl1(const int* __restrict__ nodes1,
                           const int* __restrict__ nodes2,
                           const int* __restrict__ nbr_out,
                           const int* __restrict__ nbr_in,
                           ColsAll cols) {
    int tid = blockIdx.x * blockDim.x + threadIdx.x;
    const int total = 2 * ROWS1;
    if (tid >= total) return;
    int set = tid / ROWS1;
    int rem = tid - set * ROWS1;
    int i = rem / (2 * NN1);
    int j = rem - i * (2 * NN1);
    int node = (set ? nodes2 : nodes1)[i];
    int col;
    const int* nbr;
    if (j < NN1) { col = cols.out0[set][j];        nbr = nbr_out; }
    else         { col = cols.in0[set][j - NN1];   nbr = nbr_in;  }
    g_lvl1[set][rem] = nbr[(size_t)node * MAXDEG + col];
}

__global__ void build_lvl2(const int* __restrict__ nbr_out,
                           const int* __restrict__ nbr_in,
                           ColsAll cols) {
    int tid = blockIdx.x * blockDim.x + threadIdx.x;
    const int total = 2 * ROWS2;
    if (tid >= total) return;
    int set = tid / ROWS2;
    int rem = tid - set * ROWS2;
    int r = rem / (2 * NN0);
    int j = rem - r * (2 * NN0);
    int parent = g_lvl1[set][r];
    int col;
    const int* nbr;
    if (j < NN0) { col = cols.out1[set][j];        nbr = nbr_out; }
    else         { col = cols.in1[set][j - NN0];   nbr = nbr_in;  }
    g_lvl2[set][rem] = nbr[(size_t)parent * MAXDEG + col];
}

// Pre-split W_in into tf32 hi/lo
__global__ void prep_w(const float* __restrict__ W) {
    int idx = blockIdx.x * blockDim.x + threadIdx.x;
    float w = W[idx];
    unsigned h = tf32_rna(w);
    float fh = __uint_as_float(h);
    g_Whi[idx] = fh;
    g_Wlo[idx] = __uint_as_float(tf32_rna(w - fh));
}

// ---------------------------------------------------------------------------
// Fused level-0 big path: gather+mean -> smem A[64][388], then
// sigmoid(A @ W_in) via 3xTF32 MMA -> g_h11.  Grid 400, block 256.
// ---------------------------------------------------------------------------
__global__ void __launch_bounds__(256, 2)
fused_l0(const float* __restrict__ feat) {
    extern __shared__ float sm[];
    float* As = sm;                 // [RPB][ASTRIDE]
    float* Bs = sm + SM_A;          // [hi|lo][8][128] swizzled, single buffer

    const int t    = threadIdx.x;
    const int lane = t & 31;
    const int w    = t >> 5;
    const int r0   = blockIdx.x * RPB;

    // ---- Phase 1: gather + mean into smem ----
    const float4* feat4 = reinterpret_cast<const float4*>(feat);
    const float inv = 1.0f / (float)NN0;
#pragma unroll
    for (int rr = 0; rr < RPB / 8; rr++) {
        int r = w * (RPB / 8) + rr;
        int R = r0 + r;
        int set = (R >= ROWS1) ? 1 : 0;
        int i = R - set * ROWS1;
        int self = g_lvl1[set][i];
        const int* l2 = &g_lvl2[set][i * 2 * NN0];

        float4 vs = feat4[(size_t)self * 32 + lane];
        float4 ao = make_float4(0.f, 0.f, 0.f, 0.f);
        float4 ai = make_float4(0.f, 0.f, 0.f, 0.f);
#pragma unroll
        for (int j = 0; j < NN0; j++) {
            float4 v = feat4[(size_t)l2[j] * 32 + lane];
            ao.x += v.x; ao.y += v.y; ao.z += v.z; ao.w += v.w;
        }
#pragma unroll
        for (int j = NN0; j < 2 * NN0; j++) {
            float4 v = feat4[(size_t)l2[j] * 32 + lane];
            ai.x += v.x; ai.y += v.y; ai.z += v.z; ai.w += v.w;
        }
        float* arow = &As[r * ASTRIDE];
        *reinterpret_cast<float4*>(&arow[lane * 4]) = vs;
        float4 mo = make_float4(ao.x * inv, ao.y * inv, ao.z * inv, ao.w * inv);
        float4 mi = make_float4(ai.x * inv, ai.y * inv, ai.z * inv, ai.w * inv);
        *reinterpret_cast<float4*>(&arow[128 + lane * 4]) = mo;
        *reinterpret_cast<float4*>(&arow[256 + lane * 4]) = mi;
    }

    // ---- Phase 2: 3xTF32 MMA, single-buffered pre-split W panels ----
    const int group = lane >> 2;
    const int tid4  = lane & 3;
    const int R0w   = (w & 3) * 16;
    const int C0    = (w >> 2) * 64;

    float acc[8][4];
#pragma unroll
    for (int j = 0; j < 8; j++)
#pragma unroll
        for (int q = 0; q < 4; q++) acc[j][q] = 0.f;

    const int pk = t >> 5;
    const int pn = (t & 31) * 4;
    const int sb = pk * 128 + (pn ^ (pk * 8));

    // B smem read offsets are loop-invariant (single buffer) -> hoisted
    const int ob0 = tid4 * 128;
    const int ob1 = (tid4 + 4) * 128;
    const int xr0 = tid4 * 8;
    const int xr1 = (tid4 + 4) * 8;

    float4 whi = *reinterpret_cast<const float4*>(&g_Whi[pk * EDIM + pn]);
    float4 wlo = *reinterpret_cast<const float4*>(&g_Wlo[pk * EDIM + pn]);

    const int NP = KDIM / 8;   // 48
    for (int p = 0; p < NP; p++) {
        __syncthreads();   // prev panel consumed (and As ready at p=0)
        *reinterpret_cast<float4*>(&Bs[sb])       = whi;
        *reinterpret_cast<float4*>(&Bs[BSZ + sb]) = wlo;
        __syncthreads();   // panel visible
        if (p + 1 < NP) {
            whi = *reinterpret_cast<const float4*>(
                &g_Whi[((p + 1) * 8 + pk) * EDIM + pn]);
            wlo = *reinterpret_cast<const float4*>(
                &g_Wlo[((p + 1) * 8 + pk) * EDIM + pn]);
        }

        // A fragment (m16 x k8)
        const float* ar  = &As[(R0w + group) * ASTRIDE + p * 8];
        const float* ar8 = ar + 8 * ASTRIDE;
        float x00 = ar[tid4];
        float x10 = ar8[tid4];
        float x01 = ar[tid4 + 4];
        float x11 = ar8[tid4 + 4];
        unsigned ah0 = tf32_rna(x00), ah1 = tf32_rna(x10),
                 ah2 = tf32_rna(x01), ah3 = tf32_rna(x11);
        unsigned al0 = tf32_rna(x00 - __uint_as_float(ah0));
        unsigned al1 = tf32_rna(x10 - __uint_as_float(ah1));
        unsigned al2 = tf32_rna(x01 - __uint_as_float(ah2));
        unsigned al3 = tf32_rna(x11 - __uint_as_float(ah3));

#pragma unroll
        for (int j = 0; j < 8; j++) {
            int nl = C0 + j * 8 + group;
            unsigned bh0 = __float_as_uint(Bs[ob0 + (nl ^ xr0)]);
            unsigned bh1 = __float_as_uint(Bs[ob1 + (nl ^ xr1)]);
            unsigned bl0 = __float_as_uint(Bs[BSZ + ob0 + (nl ^ xr0)]);
            unsigned bl1 = __float_as_uint(Bs[BSZ + ob1 + (nl ^ xr1)]);
            mma_tf32(acc[j], ah0, ah1, ah2, ah3, bh0, bh1);
            mma_tf32(acc[j], al0, al1, al2, al3, bh0, bh1);
            mma_tf32(acc[j], ah0, ah1, ah2, ah3, bl0, bl1);
        }
    }

    // ---- Epilogue: sigmoid + store ----
    const int Ra = r0 + R0w + group;
    const int Rb = Ra + 8;
#pragma unroll
    for (int j = 0; j < 8; j++) {
        int col = C0 + j * 8 + 2 * tid4;
        float2 oa, ob;
        oa.x = sigmoidf_stable(acc[j][0]);
        oa.y = sigmoidf_stable(acc[j][1]);
        ob.x = sigmoidf_stable(acc[j][2]);
        ob.y = sigmoidf_stable(acc[j][3]);
        *reinterpret_cast<float2*>(&g_h11[(size_t)Ra * EDIM + col]) = oa;
        *reinterpret_cast<float2*>(&g_h11[(size_t)Rb * EDIM + col]) = ob;
    }
}

// ---------------------------------------------------------------------------
// Small path kernels (512 rows), warp-per-row float4
// ---------------------------------------------------------------------------
__global__ void agg_hop0(const float* __restrict__ feat,
                         const int* __restrict__ nodes1,
                         const int* __restrict__ nodes2) {
    int t = threadIdx.x, lane = t & 31, w = t >> 5;
    int r = blockIdx.x * 8 + w;
    int set = r >> 8, i = r & 255;
    int self = (set ? nodes2 : nodes1)[i];
    const int* l1 = &g_lvl1[set][i * 2 * NN1];
    const float4* feat4 = reinterpret_cast<const float4*>(feat);
    const float inv = 1.0f / (float)NN1;

    float4 vs = feat4[(size_t)self * 32 + lane];
    float4 ao = make_float4(0.f, 0.f, 0.f, 0.f);
    float4 ai = make_float4(0.f, 0.f, 0.f, 0.f);
#pragma unroll
    for (int j = 0; j < NN1; j++) {
        float4 v = feat4[(size_t)l1[j] * 32 + lane];
        ao.x += v.x; ao.y += v.y; ao.z += v.z; ao.w += v.w;
    }
#pragma unroll
    for (int j = NN1; j < 2 * NN1; j++) {
        float4 v = feat4[(size_t)l1[j] * 32 + lane];
        ai.x += v.x; ai.y += v.y; ai.z += v.z; ai.w += v.w;
    }
    float* a = &g_agg0[(size_t)r * KDIM];
    *reinterpret_cast<float4*>(&a[lane * 4]) = vs;
    *reinterpret_cast<float4*>(&a[128 + lane * 4]) =
        make_float4(ao.x * inv, ao.y * inv, ao.z * inv, ao.w * inv);
    *reinterpret_cast<float4*>(&a[256 + lane * 4]) =
        make_float4(ai.x * inv, ai.y * inv, ai.z * inv, ai.w * inv);
}

__global__ void agg_l1() {
    int t = threadIdx.x, lane = t & 31, w = t >> 5;
    int r = blockIdx.x * 8 + w;
    int set = r >> 8, i = r & 255;
    const float4* h4 = reinterpret_cast<const float4*>(
        &g_h11[(size_t)(set * ROWS1 + i * 2 * NN1) * EDIM]);
    const float inv = 1.0f / (float)NN1;

    float4 ao = make_float4(0.f, 0.f, 0.f, 0.f);
    float4 ai = make_float4(0.f, 0.f, 0.f, 0.f);
#pragma unroll
    for (int j = 0; j < NN1; j++) {
        float4 v = h4[(size_t)j * 32 + lane];
        ao.x += v.x; ao.y += v.y; ao.z += v.z; ao.w += v.w;
    }
#pragma unroll
    for (int j = NN1; j < 2 * NN1; j++) {
        float4 v = h4[(size_t)j * 32 + lane];
        ai.x += v.x; ai.y += v.y; ai.z += v.z; ai.w += v.w;
    }
    float4 vs = reinterpret_cast<const float4*>(&g_h10[(size_t)r * EDIM])[lane];
    float* a = &g_aggL1[(size_t)r * KDIM];
    *reinterpret_cast<float4*>(&a[lane * 4]) = vs;
    *reinterpret_cast<float4*>(&a[128 + lane * 4]) =
        make_float4(ao.x * inv, ao.y * inv, ao.z * inv, ao.w * inv);
    *reinterpret_cast<float4*>(&a[256 + lane * 4]) =
        make_float4(ai.x * inv, ai.y * inv, ai.z * inv, ai.w * inv);
}

// Small GEMM+sigmoid, M-tile = 16 for grid parallelism:
// C[M,128] = sigmoid(A[M,384] @ W[384,128])
//   mode=1: A=g_agg0  -> C=g_h10      grid (32, 1)
//   mode=2: A=g_aggL1 -> C=g_hhead3[y] grid (32, 3)
__global__ void __launch_bounds__(256)
gemm_sig(const float* __restrict__ W0, const float* __restrict__ W1,
         const float* __restrict__ W2, int mode) {
    const float* A = (mode == 1) ? g_agg0 : g_aggL1;
    const float* W = (mode == 1) ? W0
                   : (blockIdx.y == 0 ? W0 : (blockIdx.y == 1 ? W1 : W2));
    float* C = (mode == 1) ? g_h10 : g_hhead3[blockIdx.y];

    __shared__ float As[16][17];    // [k][m], padded
    __shared__ float Bs[16][128];

    const int t  = threadIdx.x;
    const int tx = t & 31;          // col group (4 cols)
    const int ty = t >> 5;          // row group (2 rows)
    const int m0 = blockIdx.x * 16;

    float acc[2][4];
#pragma unroll
    for (int i = 0; i < 2; i++)
#pragma unroll
        for (int q = 0; q < 4; q++) acc[i][q] = 0.f;

    for (int k0 = 0; k0 < KDIM; k0 += 16) {
        if (t < 64) {
            int m  = t >> 2;
            int kq = (t & 3) * 4;
            float4 v = *reinterpret_cast<const float4*>(
                &A[(size_t)(m0 + m) * KDIM + k0 + kq]);
            As[kq + 0][m] = v.x;
            As[kq + 1][m] = v.y;
            As[kq + 2][m] = v.z;
            As[kq + 3][m] = v.w;
        }
#pragma unroll
        for (int l = 0; l < 2; l++) {
            int f4 = t * 2 + l;
            int k  = f4 >> 5;
            int c  = (f4 & 31) * 4;
            *reinterpret_cast<float4*>(&Bs[k][c]) =
                *reinterpret_cast<const float4*>(&W[(size_t)(k0 + k) * EDIM + c]);
        }
        __syncthreads();
#pragma unroll
        for (int k = 0; k < 16; k++) {
            float4 b = *reinterpret_cast<const float4*>(&Bs[k][tx * 4]);
            float a0 = As[k][ty * 2];
            float a1 = As[k][ty * 2 + 1];
            acc[0][0] += a0 * b.x; acc[0][1] += a0 * b.y;
            acc[0][2] += a0 * b.z; acc[0][3] += a0 * b.w;
            acc[1][0] += a1 * b.x; acc[1][1] += a1 * b.y;
            acc[1][2] += a1 * b.z; acc[1][3] += a1 * b.w;
        }
        __syncthreads();
    }

#pragma unroll
    for (int i = 0; i < 2; i++) {
        int row = m0 + ty * 2 + i;
        float4 o;
        o.x = sigmoidf_stable(acc[i][0]);
        o.y = sigmoidf_stable(acc[i][1]);
        o.z = sigmoidf_stable(acc[i][2]);
        o.w = sigmoidf_stable(acc[i][3]);
        *reinterpret_cast<float4*>(&C[(size_t)row * EDIM + tx * 4]) = o;
    }
}

// z[512,64] = g_hhead3[head] @ Wd; scatter into stacked output. grid (512, 3)
__global__ void proj3(const float* __restrict__ Wdm,
                      const float* __restrict__ Wds,
                      const float* __restrict__ Wdp,
                      float* __restrict__ out) {
    __shared__ float h[128];
    int head = blockIdx.y;
    const float* Wd = (head == 0) ? Wdm : (head == 1) ? Wds : Wdp;
    int r = blockIdx.x;
    int c = threadIdx.x;
    const float* H = g_hhead3[head];
    h[c]      = H[(size_t)r * EDIM + c];
    h[c + 64] = H[(size_t)r * EDIM + 64 + c];
    __syncthreads();
    float s = 0.f;
#pragma unroll
    for (int k = 0; k < 128; k++) s += h[k] * Wd[k * DDIM + c];
    int set = r >> 8;
    int i = r & 255;
    out[((size_t)(set * 3 + head) * BATCH + i) * DDIM + c] = s;
}

// ---------------------------------------------------------------------------
// Host-side JAX threefry reproduction (partitionable mode)
// ---------------------------------------------------------------------------
namespace tfry {

static inline uint32_t rotl32(uint32_t x, int d) { return (x << d) | (x >> (32 - d)); }

struct Key { uint32_t a, b; };

static Key threefry2x32(Key k, uint32_t x0, uint32_t x1) {
    uint32_t ks0 = k.a, ks1 = k.b, ks2 = k.a ^ k.b ^ 0x1BD11BDAu;
    x0 += ks0; x1 += ks1;
    static const int R0[4] = {13, 15, 26, 6};
    static const int R1[4] = {17, 29, 16, 24};
    auto rounds4 = [&](const int* R) {
        for (int i = 0; i < 4; i++) { x0 += x1; x1 = rotl32(x1, R[i]); x1 ^= x0; }
    };
    rounds4(R0); x0 += ks1; x1 += ks2 + 1u;
    rounds4(R1); x0 += ks2; x1 += ks0 + 2u;
    rounds4(R0); x0 += ks0; x1 += ks1 + 3u;
    rounds4(R1); x0 += ks1; x1 += ks2 + 4u;
    rounds4(R0); x0 += ks2; x1 += ks0 + 5u;
    return Key{x0, x1};
}

static Key fold(Key k, uint32_t i) { return threefry2x32(k, 0u, i); }

static void perm64_prefix(Key key, int n, int* out) {
    Key subkey = fold(key, 1);
    uint32_t bits[64];
    int idx[64];
    for (int i = 0; i < 64; i++) {
        Key r = threefry2x32(subkey, 0u, (uint32_t)i);
        bits[i] = r.a ^ r.b;
        idx[i] = i;
    }
    std::stable_sort(idx, idx + 64,
                     [&](int x, int y) { return bits[x] < bits[y]; });
    for (int j = 0; j < n; j++) out[j] = idx[j];
}

}  // namespace tfry

// ---------------------------------------------------------------------------
// kernel_launch
// ---------------------------------------------------------------------------
extern "C" void kernel_launch(void* const* d_in, const int* in_sizes, int n_in,
                              void* d_out, int out_size) {
    const int*   nodes1  = (const int*)d_in[0];
    const int*   nodes2  = (const int*)d_in[1];
    const int*   nbr_out = (const int*)d_in[2];
    const int*   nbr_in  = (const int*)d_in[3];
    const float* feat    = (const float*)d_in[4];
    const float* W_in    = (const float*)d_in[5];
    const float* W_mean  = (const float*)d_in[6];
    const float* W_std   = (const float*)d_in[7];
    const float* W_pi    = (const float*)d_in[8];
    const float* Wd_mean = (const float*)d_in[11];
    const float* Wd_std  = (const float*)d_in[12];
    const float* Wd_pi   = (const float*)d_in[13];
    float* out = (float*)d_out;

    cudaFuncSetAttribute(fused_l0, cudaFuncAttributeMaxDynamicSharedMemorySize,
                         SMEM_FUSED);

    // --- host threefry: sampling column indices ---
    ColsAll cols;
    tfry::Key root{0u, 42u};
    tfry::Key kset[2] = {tfry::fold(root, 0), tfry::fold(root, 1)};
    for (int set = 0; set < 2; set++) {
        tfry::Key key = kset[set];
        {
            tfry::Key nk = tfry::fold(key, 0);
            tfry::Key p1 = tfry::fold(key, 1);
            tfry::Key p2 = tfry::fold(key, 2);
            tfry::perm64_prefix(p1, NN1, cols.out0[set]);
            tfry::perm64_prefix(p2, NN1, cols.in0[set]);
            key = nk;
        }
        {
            tfry::Key p1 = tfry::fold(key, 1);
            tfry::Key p2 = tfry::fold(key, 2);
            tfry::perm64_prefix(p1, NN0, cols.out1[set]);
            tfry::perm64_prefix(p2, NN0, cols.in1[set]);
        }
    }

    // --- pipeline (fused_l0 at launch slot #4 for ncu capture) ---
    build_lvl1<<<(2 * ROWS1 + 255) / 256, 256>>>(nodes1, nodes2, nbr_out, nbr_in, cols);  // #1
    build_lvl2<<<(2 * ROWS2 + 255) / 256, 256>>>(nbr_out, nbr_in, cols);                  // #2
    prep_w<<<KDIM * EDIM / 256, 256>>>(W_in);                                             // #3
    fused_l0<<<ROWS_BIG / RPB, 256, SMEM_FUSED>>>(feat);                                  // #4 -> g_h11

    agg_hop0<<<64, 256>>>(feat, nodes1, nodes2);                                          // #5
    gemm_sig<<<dim3(32, 1), 256>>>(W_in, nullptr, nullptr, 1);                            // #6 -> g_h10
    agg_l1<<<64, 256>>>();                                                                // #7 -> g_aggL1
    gemm_sig<<<dim3(32, 3), 256>>>(W_mean, W_std, W_pi, 2);                               // #8 -> g_hhead3
    proj3<<<dim3(2 * BATCH, 3), 64>>>(Wd_mean, Wd_std, Wd_pi, out);                       // #9
}

// round 9
// speedup vs baseline: 1.6477x; 1.2504x over previous
#include <cuda_runtime.h>
#include <cstdint>
#include <algorithm>

// ---------------------------------------------------------------------------
// Problem constants
// ---------------------------------------------------------------------------
#define BATCH   256
#define FDIM    128
#define EDIM    128
#define DDIM    64
#define MAXDEG  64
#define NN1     25
#define NN0     10
#define ROWS1   (BATCH * 2 * NN1)     // 12800 per set
#define ROWS2   (ROWS1 * 2 * NN0)     // 256000 per set
#define ROWS_BIG (2 * ROWS1)          // 25600
#define KDIM    384

#define RPB     64                    // rows per block in fused_l0
#define ASTRIDE 388                   // 384 + 4 pad -> conflict-free A-frag LDS
#define SM_A    (RPB * ASTRIDE)       // 24832 floats
#define BSZ     (8 * 128)             // one hi 8-k panel (1024 floats)
#define SM_B    (2 * BSZ)             // double-buffered hi panels
#define SMEM_FUSED ((SM_A + SM_B) * 4)   // 107520 B (2 blocks/SM)

// ---------------------------------------------------------------------------
// Static device scratch
// ---------------------------------------------------------------------------
__device__ int   g_lvl1[2][ROWS1];
__device__ int   g_lvl2[2][ROWS2];
__device__ float g_h11[(size_t)ROWS_BIG * EDIM];      // 13.1 MB
__device__ float g_h10[2 * BATCH * EDIM];
__device__ float g_Whi[KDIM * EDIM];

struct ColsAll {
    int out0[2][NN1];
    int in0[2][NN1];
    int out1[2][NN0];
    int in1[2][NN0];
};

// ---------------------------------------------------------------------------
// Helpers
// ---------------------------------------------------------------------------
__device__ __forceinline__ float sigmoidf_stable(float x) {
    if (x >= 0.f) {
        return 1.f / (1.f + expf(-x));
    } else {
        float e = expf(x);
        return e / (1.f + e);
    }
}

__device__ __forceinline__ unsigned tf32_rna(float x) {
    unsigned r;
    asm("cvt.rna.tf32.f32 %0, %1;" : "=r"(r) : "f"(x));
    return r;
}

__device__ __forceinline__ void mma_tf32(float* c,
                                         unsigned a0, unsigned a1,
                                         unsigned a2, unsigned a3,
                                         unsigned b0, unsigned b1) {
    asm volatile(
        "mma.sync.aligned.m16n8k8.row.col.f32.tf32.tf32.f32 "
        "{%0,%1,%2,%3}, {%4,%5,%6,%7}, {%8,%9}, {%0,%1,%2,%3};"
        : "+f"(c[0]), "+f"(c[1]), "+f"(c[2]), "+f"(c[3])
        : "r"(a0), "r"(a1), "r"(a2), "r"(a3), "r"(b0), "r"(b1));
}

// ---------------------------------------------------------------------------
// Sampling index kernels
// ---------------------------------------------------------------------------
__global__ void build_lvl1(const int* __restrict__ nodes1,
                           const int* __restrict__ nodes2,
                           const int* __restrict__ nbr_out,
                           const int* __restrict__ nbr_in,
                           ColsAll cols) {
    int tid = blockIdx.x * blockDim.x + threadIdx.x;
    const int total = 2 * ROWS1;
    if (tid >= total) return;
    int set = tid / ROWS1;
    int rem = tid - set * ROWS1;
    int i = rem / (2 * NN1);
    int j = rem - i * (2 * NN1);
    int node = (set ? nodes2 : nodes1)[i];
    int col;
    const int* nbr;
    if (j < NN1) { col = cols.out0[set][j];        nbr = nbr_out; }
    else         { col = cols.in0[set][j - NN1];   nbr = nbr_in;  }
    g_lvl1[set][rem] = nbr[(size_t)node * MAXDEG + col];
}

__global__ void build_lvl2(const int* __restrict__ nbr_out,
                           const int* __restrict__ nbr_in,
                           ColsAll cols) {
    int tid = blockIdx.x * blockDim.x + threadIdx.x;
    const int total = 2 * ROWS2;
    if (tid >= total) return;
    int set = tid / ROWS2;
    int rem = tid - set * ROWS2;
    int r = rem / (2 * NN0);
    int j = rem - r * (2 * NN0);
    int parent = g_lvl1[set][r];
    int col;
    const int* nbr;
    if (j < NN0) { col = cols.out1[set][j];        nbr = nbr_out; }
    else         { col = cols.in1[set][j - NN0];   nbr = nbr_in;  }
    g_lvl2[set][rem] = nbr[(size_t)parent * MAXDEG + col];
}

// Round W_in to tf32 (hi part only; B-lo term dropped in 2-term scheme)
__global__ void prep_w(const float* __restrict__ W) {
    int idx = blockIdx.x * blockDim.x + threadIdx.x;
    g_Whi[idx] = __uint_as_float(tf32_rna(W[idx]));
}

// ---------------------------------------------------------------------------
// Fused level-0 big path: gather+mean -> smem A[64][388], then
// sigmoid(A @ W_in) via 2-term TF32 MMA (Ahi*Bhi + Alo*Bhi) -> g_h11.
// Grid 400, block 256 (8 warps: 4 row-tiles x 2 col-tiles).
// ---------------------------------------------------------------------------
__global__ void __launch_bounds__(256, 2)
fused_l0(const float* __restrict__ feat) {
    extern __shared__ float sm[];
    float* As = sm;                 // [RPB][ASTRIDE]
    float* Bs = sm + SM_A;          // [2 buf][8][128] swizzled (hi only)

    const int t    = threadIdx.x;
    const int lane = t & 31;
    const int w    = t >> 5;
    const int r0   = blockIdx.x * RPB;

    // ---- Phase 1: gather + mean into smem ----
    const float4* feat4 = reinterpret_cast<const float4*>(feat);
    const float inv = 1.0f / (float)NN0;
#pragma unroll
    for (int rr = 0; rr < RPB / 8; rr++) {
        int r = w * (RPB / 8) + rr;
        int R = r0 + r;
        int set = (R >= ROWS1) ? 1 : 0;
        int i = R - set * ROWS1;
        int self = g_lvl1[set][i];
        const int* l2 = &g_lvl2[set][i * 2 * NN0];

        float4 vs = feat4[(size_t)self * 32 + lane];
        float4 ao = make_float4(0.f, 0.f, 0.f, 0.f);
        float4 ai = make_float4(0.f, 0.f, 0.f, 0.f);
#pragma unroll
        for (int j = 0; j < NN0; j++) {
            float4 v = feat4[(size_t)l2[j] * 32 + lane];
            ao.x += v.x; ao.y += v.y; ao.z += v.z; ao.w += v.w;
        }
#pragma unroll
        for (int j = NN0; j < 2 * NN0; j++) {
            float4 v = feat4[(size_t)l2[j] * 32 + lane];
            ai.x += v.x; ai.y += v.y; ai.z += v.z; ai.w += v.w;
        }
        float* arow = &As[r * ASTRIDE];
        *reinterpret_cast<float4*>(&arow[lane * 4]) = vs;
        float4 mo = make_float4(ao.x * inv, ao.y * inv, ao.z * inv, ao.w * inv);
        float4 mi = make_float4(ai.x * inv, ai.y * inv, ai.z * inv, ai.w * inv);
        *reinterpret_cast<float4*>(&arow[128 + lane * 4]) = mo;
        *reinterpret_cast<float4*>(&arow[256 + lane * 4]) = mi;
    }

    // ---- Phase 2: 2-term TF32 MMA, double-buffered hi panels ----
    const int group = lane >> 2;
    const int tid4  = lane & 3;
    const int R0w   = (w & 3) * 16;
    const int C0    = (w >> 2) * 64;

    float acc[8][4];
#pragma unroll
    for (int j = 0; j < 8; j++)
#pragma unroll
        for (int q = 0; q < 4; q++) acc[j][q] = 0.f;

    const int pk = t >> 5;
    const int pn = (t & 31) * 4;
    const int sb = pk * 128 + (pn ^ (pk * 8));

    const int ob0 = tid4 * 128;
    const int ob1 = (tid4 + 4) * 128;
    const int xr0 = tid4 * 8;
    const int xr1 = (tid4 + 4) * 8;

    float4 whi = *reinterpret_cast<const float4*>(&g_Whi[pk * EDIM + pn]);
    __syncthreads();   // As complete
    *reinterpret_cast<float4*>(&Bs[sb]) = whi;                   // panel 0 -> buf 0
    whi = *reinterpret_cast<const float4*>(&g_Whi[(8 + pk) * EDIM + pn]);
    __syncthreads();   // buf 0 visible

    const int NP = KDIM / 8;   // 48
    for (int p = 0; p < NP; p++) {
        const float* buf = &Bs[(p & 1) * BSZ];

        // stage next panel into the other buffer (no reader conflict)
        if (p + 1 < NP) {
            *reinterpret_cast<float4*>(&Bs[((p + 1) & 1) * BSZ + sb]) = whi;
            if (p + 2 < NP) {
                whi = *reinterpret_cast<const float4*>(
                    &g_Whi[((p + 2) * 8 + pk) * EDIM + pn]);
            }
        }

        // A fragment (m16 x k8), hi + lo split
        const float* ar  = &As[(R0w + group) * ASTRIDE + p * 8];
        const float* ar8 = ar + 8 * ASTRIDE;
        float x00 = ar[tid4];
        float x10 = ar8[tid4];
        float x01 = ar[tid4 + 4];
        float x11 = ar8[tid4 + 4];
        unsigned ah0 = tf32_rna(x00), ah1 = tf32_rna(x10),
                 ah2 = tf32_rna(x01), ah3 = tf32_rna(x11);
        unsigned al0 = tf32_rna(x00 - __uint_as_float(ah0));
        unsigned al1 = tf32_rna(x10 - __uint_as_float(ah1));
        unsigned al2 = tf32_rna(x01 - __uint_as_float(ah2));
        unsigned al3 = tf32_rna(x11 - __uint_as_float(ah3));

#pragma unroll
        for (int j = 0; j < 8; j++) {
            int nl = C0 + j * 8 + group;
            unsigned bh0 = __float_as_uint(buf[ob0 + (nl ^ xr0)]);
            unsigned bh1 = __float_as_uint(buf[ob1 + (nl ^ xr1)]);
            mma_tf32(acc[j], ah0, ah1, ah2, ah3, bh0, bh1);
            mma_tf32(acc[j], al0, al1, al2, al3, bh0, bh1);
        }
        __syncthreads();   // staging visible / buf consumed
    }

    // ---- Epilogue: sigmoid + store ----
    const int Ra = r0 + R0w + group;
    const int Rb = Ra + 8;
#pragma unroll
    for (int j = 0; j < 8; j++) {
        int col = C0 + j * 8 + 2 * tid4;
        float2 oa, ob;
        oa.x = sigmoidf_stable(acc[j][0]);
        oa.y = sigmoidf_stable(acc[j][1]);
        ob.x = sigmoidf_stable(acc[j][2]);
        ob.y = sigmoidf_stable(acc[j][3]);
        *reinterpret_cast<float2*>(&g_h11[(size_t)Ra * EDIM + col]) = oa;
        *reinterpret_cast<float2*>(&g_h11[(size_t)Rb * EDIM + col]) = ob;
    }
}

// ---------------------------------------------------------------------------
// fused_s1: hop-0 gather+mean + GEMM(W_in)+sigmoid -> g_h10.
// Grid 64, block 256; 8 rows per block (warp per row gather).
// ---------------------------------------------------------------------------
__global__ void __launch_bounds__(256)
fused_s1(const float* __restrict__ feat,
         const int* __restrict__ nodes1,
         const int* __restrict__ nodes2,
         const float* __restrict__ W) {
    __shared__ float As[8 * ASTRIDE];
    __shared__ float Bs[16][128];

    const int t = threadIdx.x, lane = t & 31, w = t >> 5;

    // ---- gather (warp w -> row w) ----
    {
        int R = blockIdx.x * 8 + w;        // 0..511
        int set = R >> 8, i = R & 255;
        int self = (set ? nodes2 : nodes1)[i];
        const int* l1 = &g_lvl1[set][i * 2 * NN1];
        const float4* feat4 = reinterpret_cast<const float4*>(feat);
        const float inv = 1.0f / (float)NN1;

        float4 vs = feat4[(size_t)self * 32 + lane];
        float4 ao = make_float4(0.f, 0.f, 0.f, 0.f);
        float4 ai = make_float4(0.f, 0.f, 0.f, 0.f);
#pragma unroll
        for (int j = 0; j < NN1; j++) {
            float4 v = feat4[(size_t)l1[j] * 32 + lane];
            ao.x += v.x; ao.y += v.y; ao.z += v.z; ao.w += v.w;
        }
#pragma unroll
        for (int j = NN1; j < 2 * NN1; j++) {
            float4 v = feat4[(size_t)l1[j] * 32 + lane];
            ai.x += v.x; ai.y += v.y; ai.z += v.z; ai.w += v.w;
        }
        float* arow = &As[w * ASTRIDE];
        *reinterpret_cast<float4*>(&arow[lane * 4]) = vs;
        *reinterpret_cast<float4*>(&arow[128 + lane * 4]) =
            make_float4(ao.x * inv, ao.y * inv, ao.z * inv, ao.w * inv);
        *reinterpret_cast<float4*>(&arow[256 + lane * 4]) =
            make_float4(ai.x * inv, ai.y * inv, ai.z * inv, ai.w * inv);
    }
    __syncthreads();

    // ---- GEMM: row = w (t>>5), cols (t&31)*4 ----
    const int tx = t & 31;
    float acc[4] = {0.f, 0.f, 0.f, 0.f};

    for (int k0 = 0; k0 < KDIM; k0 += 16) {
#pragma unroll
        for (int l = 0; l < 2; l++) {
            int f4 = t * 2 + l;
            int k  = f4 >> 5;
            int c  = (f4 & 31) * 4;
            *reinterpret_cast<float4*>(&Bs[k][c]) =
                *reinterpret_cast<const float4*>(&W[(size_t)(k0 + k) * EDIM + c]);
        }
        __syncthreads();
#pragma unroll
        for (int k = 0; k < 16; k++) {
            float4 b = *reinterpret_cast<const float4*>(&Bs[k][tx * 4]);
            float a = As[w * ASTRIDE + k0 + k];
            acc[0] += a * b.x; acc[1] += a * b.y;
            acc[2] += a * b.z; acc[3] += a * b.w;
        }
        __syncthreads();
    }

    int R = blockIdx.x * 8 + w;
    float4 o;
    o.x = sigmoidf_stable(acc[0]);
    o.y = sigmoidf_stable(acc[1]);
    o.z = sigmoidf_stable(acc[2]);
    o.w = sigmoidf_stable(acc[3]);
    *reinterpret_cast<float4*>(&g_h10[(size_t)R * EDIM + tx * 4]) = o;
}

// ---------------------------------------------------------------------------
// fused_s2: layer-1 agg (from h10/h11) + head GEMM+sigmoid + projection -> out
// Grid (64, 3): blockIdx.y = head. 8 rows per block.
// ---------------------------------------------------------------------------
__global__ void __launch_bounds__(256)
fused_s2(const float* __restrict__ Wm, const float* __restrict__ Ws,
         const float* __restrict__ Wp,
         const float* __restrict__ Wdm, const float* __restrict__ Wds,
         const float* __restrict__ Wdp,
         float* __restrict__ out) {
    __shared__ float As[8 * ASTRIDE];
    __shared__ float Bs[16][128];
    __shared__ float Hs[8 * 132];

    const int t = threadIdx.x, lane = t & 31, w = t >> 5;
    const int head = blockIdx.y;
    const float* W  = (head == 0) ? Wm  : (head == 1) ? Ws  : Wp;
    const float* Wd = (head == 0) ? Wdm : (head == 1) ? Wds : Wdp;

    // ---- layer-1 aggregation (warp w -> row w) ----
    {
        int R = blockIdx.x * 8 + w;
        int set = R >> 8, i = R & 255;
        const float4* h4 = reinterpret_cast<const float4*>(
            &g_h11[(size_t)(set * ROWS1 + i * 2 * NN1) * EDIM]);
        const float inv = 1.0f / (float)NN1;

        float4 vs = reinterpret_cast<const float4*>(&g_h10[(size_t)R * EDIM])[lane];
        float4 ao = make_float4(0.f, 0.f, 0.f, 0.f);
        float4 ai = make_float4(0.f, 0.f, 0.f, 0.f);
#pragma unroll
        for (int j = 0; j < NN1; j++) {
            float4 v = h4[(size_t)j * 32 + lane];
            ao.x += v.x; ao.y += v.y; ao.z += v.z; ao.w += v.w;
        }
#pragma unroll
        for (int j = NN1; j < 2 * NN1; j++) {
            float4 v = h4[(size_t)j * 32 + lane];
            ai.x += v.x; ai.y += v.y; ai.z += v.z; ai.w += v.w;
        }
        float* arow = &As[w * ASTRIDE];
        *reinterpret_cast<float4*>(&arow[lane * 4]) = vs;
        *reinterpret_cast<float4*>(&arow[128 + lane * 4]) =
            make_float4(ao.x * inv, ao.y * inv, ao.z * inv, ao.w * inv);
        *reinterpret_cast<float4*>(&arow[256 + lane * 4]) =
            make_float4(ai.x * inv, ai.y * inv, ai.z * inv, ai.w * inv);
    }
    __syncthreads();

    // ---- head GEMM + sigmoid -> Hs ----
    const int tx = t & 31;
    float acc[4] = {0.f, 0.f, 0.f, 0.f};

    for (int k0 = 0; k0 < KDIM; k0 += 16) {
#pragma unroll
        for (int l = 0; l < 2; l++) {
            int f4 = t * 2 + l;
            int k  = f4 >> 5;
            int c  = (f4 & 31) * 4;
            *reinterpret_cast<float4*>(&Bs[k][c]) =
                *reinterpret_cast<const float4*>(&W[(size_t)(k0 + k) * EDIM + c]);
        }
        __syncthreads();
#pragma unroll
        for (int k = 0; k < 16; k++) {
            float4 b = *reinterpret_cast<const float4*>(&Bs[k][tx * 4]);
            float a = As[w * ASTRIDE + k0 + k];
            acc[0] += a * b.x; acc[1] += a * b.y;
            acc[2] += a * b.z; acc[3] += a * b.w;
        }
        __syncthreads();
    }

    {
        float4 o;
        o.x = sigmoidf_stable(acc[0]);
        o.y = sigmoidf_stable(acc[1]);
        o.z = sigmoidf_stable(acc[2]);
        o.w = sigmoidf_stable(acc[3]);
        *reinterpret_cast<float4*>(&Hs[w * 132 + tx * 4]) = o;
    }
    __syncthreads();

    // ---- projection: z[8][64] = Hs[8][128] @ Wd[128][64] ----
    {
        int r  = t >> 5;          // row 0..7
        int cg = t & 31;          // col pair
        float s0 = 0.f, s1 = 0.f;
#pragma unroll
        for (int k = 0; k < 128; k++) {
            float hv = Hs[r * 132 + k];
            float2 wd = *reinterpret_cast<const float2*>(&Wd[k * DDIM + cg * 2]);
            s0 += hv * wd.x;
            s1 += hv * wd.y;
        }
        int R = blockIdx.x * 8 + r;
        int set = R >> 8, i = R & 255;
        float2 z = make_float2(s0, s1);
        *reinterpret_cast<float2*>(
            &out[((size_t)(set * 3 + head) * BATCH + i) * DDIM + cg * 2]) = z;
    }
}

// ---------------------------------------------------------------------------
// Host-side JAX threefry reproduction (partitionable mode)
// ---------------------------------------------------------------------------
namespace tfry {

static inline uint32_t rotl32(uint32_t x, int d) { return (x << d) | (x >> (32 - d)); }

struct Key { uint32_t a, b; };

static Key threefry2x32(Key k, uint32_t x0, uint32_t x1) {
    uint32_t ks0 = k.a, ks1 = k.b, ks2 = k.a ^ k.b ^ 0x1BD11BDAu;
    x0 += ks0; x1 += ks1;
    static const int R0[4] = {13, 15, 26, 6};
    static const int R1[4] = {17, 29, 16, 24};
    auto rounds4 = [&](const int* R) {
        for (int i = 0; i < 4; i++) { x0 += x1; x1 = rotl32(x1, R[i]); x1 ^= x0; }
    };
    rounds4(R0); x0 += ks1; x1 += ks2 + 1u;
    rounds4(R1); x0 += ks2; x1 += ks0 + 2u;
    rounds4(R0); x0 += ks0; x1 += ks1 + 3u;
    rounds4(R1); x0 += ks1; x1 += ks2 + 4u;
    rounds4(R0); x0 += ks2; x1 += ks0 + 5u;
    return Key{x0, x1};
}

static Key fold(Key k, uint32_t i) { return threefry2x32(k, 0u, i); }

static void perm64_prefix(Key key, int n, int* out) {
    Key subkey = fold(key, 1);
    uint32_t bits[64];
    int idx[64];
    for (int i = 0; i < 64; i++) {
        Key r = threefry2x32(subkey, 0u, (uint32_t)i);
        bits[i] = r.a ^ r.b;
        idx[i] = i;
    }
    std::stable_sort(idx, idx + 64,
                     [&](int x, int y) { return bits[x] < bits[y]; });
    for (int j = 0; j < n; j++) out[j] = idx[j];
}

}  // namespace tfry

// ---------------------------------------------------------------------------
// kernel_launch
// ---------------------------------------------------------------------------
extern "C" void kernel_launch(void* const* d_in, const int* in_sizes, int n_in,
                              void* d_out, int out_size) {
    const int*   nodes1  = (const int*)d_in[0];
    const int*   nodes2  = (const int*)d_in[1];
    const int*   nbr_out = (const int*)d_in[2];
    const int*   nbr_in  = (const int*)d_in[3];
    const float* feat    = (const float*)d_in[4];
    const float* W_in    = (const float*)d_in[5];
    const float* W_mean  = (const float*)d_in[6];
    const float* W_std   = (const float*)d_in[7];
    const float* W_pi    = (const float*)d_in[8];
    const float* Wd_mean = (const float*)d_in[11];
    const float* Wd_std  = (const float*)d_in[12];
    const float* Wd_pi   = (const float*)d_in[13];
    float* out = (float*)d_out;

    cudaFuncSetAttribute(fused_l0, cudaFuncAttributeMaxDynamicSharedMemorySize,
                         SMEM_FUSED);

    // --- host threefry: sampling column indices ---
    ColsAll cols;
    tfry::Key root{0u, 42u};
    tfry::Key kset[2] = {tfry::fold(root, 0), tfry::fold(root, 1)};
    for (int set = 0; set < 2; set++) {
        tfry::Key key = kset[set];
        {
            tfry::Key nk = tfry::fold(key, 0);
            tfry::Key p1 = tfry::fold(key, 1);
            tfry::Key p2 = tfry::fold(key, 2);
            tfry::perm64_prefix(p1, NN1, cols.out0[set]);
            tfry::perm64_prefix(p2, NN1, cols.in0[set]);
            key = nk;
        }
        {
            tfry::Key p1 = tfry::fold(key, 1);
            tfry::Key p2 = tfry::fold(key, 2);
            tfry::perm64_prefix(p1, NN0, cols.out1[set]);
            tfry::perm64_prefix(p2, NN0, cols.in1[set]);
        }
    }

    // --- pipeline (fused_l0 at launch slot #4 for ncu capture) ---
    build_lvl1<<<(2 * ROWS1 + 255) / 256, 256>>>(nodes1, nodes2, nbr_out, nbr_in, cols);  // #1
    build_lvl2<<<(2 * ROWS2 + 255) / 256, 256>>>(nbr_out, nbr_in, cols);                  // #2
    prep_w<<<KDIM * EDIM / 256, 256>>>(W_in);                                             // #3
    fused_l0<<<ROWS_BIG / RPB, 256, SMEM_FUSED>>>(feat);                                  // #4 -> g_h11

    fused_s1<<<64, 256>>>(feat, nodes1, nodes2, W_in);                                    // #5 -> g_h10
    fused_s2<<<dim3(64, 3), 256>>>(W_mean, W_std, W_pi,
                                   Wd_mean, Wd_std, Wd_pi, out);                          // #6 -> out
}

// round 10
// speedup vs baseline: 1.9394x; 1.1770x over previous
#include <cuda_runtime.h>
#include <cstdint>
#include <algorithm>

// ---------------------------------------------------------------------------
// Problem constants
// ---------------------------------------------------------------------------
#define BATCH   256
#define FDIM    128
#define EDIM    128
#define DDIM    64
#define MAXDEG  64
#define NN1     25
#define NN0     10
#define ROWS1   (BATCH * 2 * NN1)     // 12800 per set
#define ROWS2   (ROWS1 * 2 * NN0)     // 256000 per set
#define ROWS_BIG (2 * ROWS1)          // 25600
#define KDIM    384

#define RPB     64                    // rows per block in fused_l0
#define ASTRIDE 388                   // 384 + 4 pad -> conflict-free A-frag LDS
#define SM_A    (RPB * ASTRIDE)       // 24832 floats
#define BSZ     (8 * 128)             // one hi 8-k panel (1024 floats)
#define SM_B    (2 * BSZ)             // double-buffered hi panels
#define SMEM_FUSED ((SM_A + SM_B) * 4)   // 107520 B (2 blocks/SM)

#define L0_BLOCKS (ROWS_BIG / RPB)    // 400
#define S1_BLOCKS 64
#define PREP_BLOCKS (KDIM * EDIM / 256)   // 192
#define B1_BLOCKS ((2 * ROWS1 + 255) / 256) // 100

// ---------------------------------------------------------------------------
// Static device scratch
// ---------------------------------------------------------------------------
__device__ int   g_lvl1[2][ROWS1];
__device__ int   g_lvl2[2][ROWS2];
__device__ float g_h11[(size_t)ROWS_BIG * EDIM];      // 13.1 MB
__device__ float g_h10[2 * BATCH * EDIM];
__device__ float g_Whi[KDIM * EDIM];

struct ColsAll {
    int out0[2][NN1];
    int in0[2][NN1];
    int out1[2][NN0];
    int in1[2][NN0];
};

// ---------------------------------------------------------------------------
// Helpers
// ---------------------------------------------------------------------------
__device__ __forceinline__ float sigmoidf_stable(float x) {
    if (x >= 0.f) {
        return 1.f / (1.f + expf(-x));
    } else {
        float e = expf(x);
        return e / (1.f + e);
    }
}

__device__ __forceinline__ unsigned tf32_rna(float x) {
    unsigned r;
    asm("cvt.rna.tf32.f32 %0, %1;" : "=r"(r) : "f"(x));
    return r;
}

__device__ __forceinline__ void mma_tf32(float* c,
                                         unsigned a0, unsigned a1,
                                         unsigned a2, unsigned a3,
                                         unsigned b0, unsigned b1) {
    asm volatile(
        "mma.sync.aligned.m16n8k8.row.col.f32.tf32.tf32.f32 "
        "{%0,%1,%2,%3}, {%4,%5,%6,%7}, {%8,%9}, {%0,%1,%2,%3};"
        : "+f"(c[0]), "+f"(c[1]), "+f"(c[2]), "+f"(c[3])
        : "r"(a0), "r"(a1), "r"(a2), "r"(a3), "r"(b0), "r"(b1));
}

// ---------------------------------------------------------------------------
// #1: build_lvl1 + prep_w combined (independent work, one launch)
// ---------------------------------------------------------------------------
__global__ void comb_b1_prep(const int* __restrict__ nodes1,
                             const int* __restrict__ nodes2,
                             const int* __restrict__ nbr_out,
                             const int* __restrict__ nbr_in,
                             const float* __restrict__ W,
                             ColsAll cols) {
    if (blockIdx.x < PREP_BLOCKS) {
        int idx = blockIdx.x * 256 + threadIdx.x;
        g_Whi[idx] = __uint_as_float(tf32_rna(W[idx]));
        return;
    }
    int tid = (blockIdx.x - PREP_BLOCKS) * 256 + threadIdx.x;
    const int total = 2 * ROWS1;
    if (tid >= total) return;
    int set = tid / ROWS1;
    int rem = tid - set * ROWS1;
    int i = rem / (2 * NN1);
    int j = rem - i * (2 * NN1);
    int node = (set ? nodes2 : nodes1)[i];
    int col;
    const int* nbr;
    if (j < NN1) { col = cols.out0[set][j];        nbr = nbr_out; }
    else         { col = cols.in0[set][j - NN1];   nbr = nbr_in;  }
    g_lvl1[set][rem] = nbr[(size_t)node * MAXDEG + col];
}

// ---------------------------------------------------------------------------
// #2: level-2 sampling indices
// ---------------------------------------------------------------------------
__global__ void build_lvl2(const int* __restrict__ nbr_out,
                           const int* __restrict__ nbr_in,
                           ColsAll cols) {
    int tid = blockIdx.x * blockDim.x + threadIdx.x;
    const int total = 2 * ROWS2;
    if (tid >= total) return;
    int set = tid / ROWS2;
    int rem = tid - set * ROWS2;
    int r = rem / (2 * NN0);
    int j = rem - r * (2 * NN0);
    int parent = g_lvl1[set][r];
    int col;
    const int* nbr;
    if (j < NN0) { col = cols.out1[set][j];        nbr = nbr_out; }
    else         { col = cols.in1[set][j - NN0];   nbr = nbr_in;  }
    g_lvl2[set][rem] = nbr[(size_t)parent * MAXDEG + col];
}

// ---------------------------------------------------------------------------
// #3: fused_l0 (blocks 0..399) + fused_s1 (blocks 400..463) in one launch.
//
// fused_l0: gather+mean -> smem A[64][388]; sigmoid(A @ W) via 2-term TF32
//           MMA with software-pipelined A fragments -> g_h11.
// fused_s1: hop-0 gather+mean + fp32 GEMM(W_in)+sigmoid -> g_h10 (independent
//           of fused_l0; rides in its spare wave-2 slots).
// ---------------------------------------------------------------------------
__global__ void __launch_bounds__(256, 2)
fused_l0s1(const float* __restrict__ feat,
           const int* __restrict__ nodes1,
           const int* __restrict__ nodes2,
           const float* __restrict__ W) {
    extern __shared__ float sm[];
    const int t    = threadIdx.x;
    const int lane = t & 31;
    const int w    = t >> 5;

    const float4* feat4 = reinterpret_cast<const float4*>(feat);

    if (blockIdx.x >= L0_BLOCKS) {
        // ================== fused_s1 path ==================
        float* As = sm;                       // [8][ASTRIDE]
        float* Bs = sm + 8 * ASTRIDE;         // [16][128]
        const int b = blockIdx.x - L0_BLOCKS; // 0..63

        {   // gather: warp w -> row w
            int R = b * 8 + w;                // 0..511
            int set = R >> 8, i = R & 255;
            int self = (set ? nodes2 : nodes1)[i];
            const int* l1 = &g_lvl1[set][i * 2 * NN1];
            const float inv = 1.0f / (float)NN1;

            float4 vs = feat4[(size_t)self * 32 + lane];
            float4 ao = make_float4(0.f, 0.f, 0.f, 0.f);
            float4 ai = make_float4(0.f, 0.f, 0.f, 0.f);
#pragma unroll
            for (int j = 0; j < NN1; j++) {
                float4 v = feat4[(size_t)l1[j] * 32 + lane];
                ao.x += v.x; ao.y += v.y; ao.z += v.z; ao.w += v.w;
            }
#pragma unroll
            for (int j = NN1; j < 2 * NN1; j++) {
                float4 v = feat4[(size_t)l1[j] * 32 + lane];
                ai.x += v.x; ai.y += v.y; ai.z += v.z; ai.w += v.w;
            }
            float* arow = &As[w * ASTRIDE];
            *reinterpret_cast<float4*>(&arow[lane * 4]) = vs;
            *reinterpret_cast<float4*>(&arow[128 + lane * 4]) =
                make_float4(ao.x * inv, ao.y * inv, ao.z * inv, ao.w * inv);
            *reinterpret_cast<float4*>(&arow[256 + lane * 4]) =
                make_float4(ai.x * inv, ai.y * inv, ai.z * inv, ai.w * inv);
        }
        __syncthreads();

        // GEMM: row = w, cols (t&31)*4
        const int tx = t & 31;
        float acc[4] = {0.f, 0.f, 0.f, 0.f};
        for (int k0 = 0; k0 < KDIM; k0 += 16) {
#pragma unroll
            for (int l = 0; l < 2; l++) {
                int f4 = t * 2 + l;
                int k  = f4 >> 5;
                int c  = (f4 & 31) * 4;
                *reinterpret_cast<float4*>(&Bs[k * 128 + c]) =
                    *reinterpret_cast<const float4*>(&W[(size_t)(k0 + k) * EDIM + c]);
            }
            __syncthreads();
#pragma unroll
            for (int k = 0; k < 16; k++) {
                float4 bv = *reinterpret_cast<const float4*>(&Bs[k * 128 + tx * 4]);
                float a = As[w * ASTRIDE + k0 + k];
                acc[0] += a * bv.x; acc[1] += a * bv.y;
                acc[2] += a * bv.z; acc[3] += a * bv.w;
            }
            __syncthreads();
        }
        int R = b * 8 + w;
        float4 o;
        o.x = sigmoidf_stable(acc[0]);
        o.y = sigmoidf_stable(acc[1]);
        o.z = sigmoidf_stable(acc[2]);
        o.w = sigmoidf_stable(acc[3]);
        *reinterpret_cast<float4*>(&g_h10[(size_t)R * EDIM + tx * 4]) = o;
        return;
    }

    // ================== fused_l0 path ==================
    float* As = sm;                 // [RPB][ASTRIDE]
    float* Bs = sm + SM_A;          // [2 buf][8][128] swizzled (hi only)
    const int r0 = blockIdx.x * RPB;

    // ---- Phase 1: gather + mean into smem ----
    const float inv = 1.0f / (float)NN0;
#pragma unroll
    for (int rr = 0; rr < RPB / 8; rr++) {
        int r = w * (RPB / 8) + rr;
        int R = r0 + r;
        int set = (R >= ROWS1) ? 1 : 0;
        int i = R - set * ROWS1;
        int self = g_lvl1[set][i];
        const int* l2 = &g_lvl2[set][i * 2 * NN0];

        float4 vs = feat4[(size_t)self * 32 + lane];
        float4 ao = make_float4(0.f, 0.f, 0.f, 0.f);
        float4 ai = make_float4(0.f, 0.f, 0.f, 0.f);
#pragma unroll
        for (int j = 0; j < NN0; j++) {
            float4 v = feat4[(size_t)l2[j] * 32 + lane];
            ao.x += v.x; ao.y += v.y; ao.z += v.z; ao.w += v.w;
        }
#pragma unroll
        for (int j = NN0; j < 2 * NN0; j++) {
            float4 v = feat4[(size_t)l2[j] * 32 + lane];
            ai.x += v.x; ai.y += v.y; ai.z += v.z; ai.w += v.w;
        }
        float* arow = &As[r * ASTRIDE];
        *reinterpret_cast<float4*>(&arow[lane * 4]) = vs;
        float4 mo = make_float4(ao.x * inv, ao.y * inv, ao.z * inv, ao.w * inv);
        float4 mi = make_float4(ai.x * inv, ai.y * inv, ai.z * inv, ai.w * inv);
        *reinterpret_cast<float4*>(&arow[128 + lane * 4]) = mo;
        *reinterpret_cast<float4*>(&arow[256 + lane * 4]) = mi;
    }

    // ---- Phase 2: 2-term TF32 MMA, double-buffered B, pipelined A frags ----
    const int group = lane >> 2;
    const int tid4  = lane & 3;
    const int R0w   = (w & 3) * 16;
    const int C0    = (w >> 2) * 64;

    float acc[8][4];
#pragma unroll
    for (int j = 0; j < 8; j++)
#pragma unroll
        for (int q = 0; q < 4; q++) acc[j][q] = 0.f;

    const int pk = t >> 5;
    const int pn = (t & 31) * 4;
    const int sb = pk * 128 + (pn ^ (pk * 8));

    const int ob0 = tid4 * 128;
    const int ob1 = (tid4 + 4) * 128;
    const int xr0 = tid4 * 8;
    const int xr1 = (tid4 + 4) * 8;

    const float* arb  = &As[(R0w + group) * ASTRIDE];
    const float* arb8 = arb + 8 * ASTRIDE;

    float4 whi = *reinterpret_cast<const float4*>(&g_Whi[pk * EDIM + pn]);
    __syncthreads();   // As complete

    // A frag for panel 0 (raw)
    float x00 = arb[tid4];
    float x10 = arb8[tid4];
    float x01 = arb[tid4 + 4];
    float x11 = arb8[tid4 + 4];

    *reinterpret_cast<float4*>(&Bs[sb]) = whi;                   // panel 0 -> buf 0
    whi = *reinterpret_cast<const float4*>(&g_Whi[(8 + pk) * EDIM + pn]);
    __syncthreads();   // buf 0 visible

    const int NP = KDIM / 8;   // 48
    for (int p = 0; p < NP; p++) {
        const float* buf = &Bs[(p & 1) * BSZ];

        // stage next B panel into the other buffer
        if (p + 1 < NP) {
            *reinterpret_cast<float4*>(&Bs[((p + 1) & 1) * BSZ + sb]) = whi;
            if (p + 2 < NP) {
                whi = *reinterpret_cast<const float4*>(
                    &g_Whi[((p + 2) * 8 + pk) * EDIM + pn]);
            }
        }

        // convert current raw A frag -> tf32 hi/lo
        unsigned ah0 = tf32_rna(x00), ah1 = tf32_rna(x10),
                 ah2 = tf32_rna(x01), ah3 = tf32_rna(x11);
        unsigned al0 = tf32_rna(x00 - __uint_as_float(ah0));
        unsigned al1 = tf32_rna(x10 - __uint_as_float(ah1));
        unsigned al2 = tf32_rna(x01 - __uint_as_float(ah2));
        unsigned al3 = tf32_rna(x11 - __uint_as_float(ah3));

        // prefetch raw A frag for next panel (overlaps with MMA below)
        if (p + 1 < NP) {
            int ko = (p + 1) * 8;
            x00 = arb[ko + tid4];
            x10 = arb8[ko + tid4];
            x01 = arb[ko + tid4 + 4];
            x11 = arb8[ko + tid4 + 4];
        }

#pragma unroll
        for (int j = 0; j < 8; j++) {
            int nl = C0 + j * 8 + group;
            unsigned bh0 = __float_as_uint(buf[ob0 + (nl ^ xr0)]);
            unsigned bh1 = __float_as_uint(buf[ob1 + (nl ^ xr1)]);
            mma_tf32(acc[j], ah0, ah1, ah2, ah3, bh0, bh1);
            mma_tf32(acc[j], al0, al1, al2, al3, bh0, bh1);
        }
        __syncthreads();   // staged panel visible / old buf consumed
    }

    // ---- Epilogue: sigmoid + store ----
    const int Ra = r0 + R0w + group;
    const int Rb = Ra + 8;
#pragma unroll
    for (int j = 0; j < 8; j++) {
        int col = C0 + j * 8 + 2 * tid4;
        float2 oa, ob;
        oa.x = sigmoidf_stable(acc[j][0]);
        oa.y = sigmoidf_stable(acc[j][1]);
        ob.x = sigmoidf_stable(acc[j][2]);
        ob.y = sigmoidf_stable(acc[j][3]);
        *reinterpret_cast<float2*>(&g_h11[(size_t)Ra * EDIM + col]) = oa;
        *reinterpret_cast<float2*>(&g_h11[(size_t)Rb * EDIM + col]) = ob;
    }
}

// ---------------------------------------------------------------------------
// #4: fused_s2: layer-1 agg + head GEMM+sigmoid + projection -> out
// Grid (64, 3): blockIdx.y = head. 8 rows per block.
// ---------------------------------------------------------------------------
__global__ void __launch_bounds__(256)
fused_s2(const float* __restrict__ Wm, const float* __restrict__ Ws,
         const float* __restrict__ Wp,
         const float* __restrict__ Wdm, const float* __restrict__ Wds,
         const float* __restrict__ Wdp,
         float* __restrict__ out) {
    __shared__ float As[8 * ASTRIDE];
    __shared__ float Bs[16][128];
    __shared__ float Hs[8 * 132];

    const int t = threadIdx.x, lane = t & 31, w = t >> 5;
    const int head = blockIdx.y;
    const float* W  = (head == 0) ? Wm  : (head == 1) ? Ws  : Wp;
    const float* Wd = (head == 0) ? Wdm : (head == 1) ? Wds : Wdp;

    // ---- layer-1 aggregation (warp w -> row w) ----
    {
        int R = blockIdx.x * 8 + w;
        int set = R >> 8, i = R & 255;
        const float4* h4 = reinterpret_cast<const float4*>(
            &g_h11[(size_t)(set * ROWS1 + i * 2 * NN1) * EDIM]);
        const float inv = 1.0f / (float)NN1;

        float4 vs = reinterpret_cast<const float4*>(&g_h10[(size_t)R * EDIM])[lane];
        float4 ao = make_float4(0.f, 0.f, 0.f, 0.f);
        float4 ai = make_float4(0.f, 0.f, 0.f, 0.f);
#pragma unroll
        for (int j = 0; j < NN1; j++) {
            float4 v = h4[(size_t)j * 32 + lane];
            ao.x += v.x; ao.y += v.y; ao.z += v.z; ao.w += v.w;
        }
#pragma unroll
        for (int j = NN1; j < 2 * NN1; j++) {
            float4 v = h4[(size_t)j * 32 + lane];
            ai.x += v.x; ai.y += v.y; ai.z += v.z; ai.w += v.w;
        }
        float* arow = &As[w * ASTRIDE];
        *reinterpret_cast<float4*>(&arow[lane * 4]) = vs;
        *reinterpret_cast<float4*>(&arow[128 + lane * 4]) =
            make_float4(ao.x * inv, ao.y * inv, ao.z * inv, ao.w * inv);
        *reinterpret_cast<float4*>(&arow[256 + lane * 4]) =
            make_float4(ai.x * inv, ai.y * inv, ai.z * inv, ai.w * inv);
    }
    __syncthreads();

    // ---- head GEMM + sigmoid -> Hs ----
    const int tx = t & 31;
    float acc[4] = {0.f, 0.f, 0.f, 0.f};

    for (int k0 = 0; k0 < KDIM; k0 += 16) {
#pragma unroll
        for (int l = 0; l < 2; l++) {
            int f4 = t * 2 + l;
            int k  = f4 >> 5;
            int c  = (f4 & 31) * 4;
            *reinterpret_cast<float4*>(&Bs[k][c]) =
                *reinterpret_cast<const float4*>(&W[(size_t)(k0 + k) * EDIM + c]);
        }
        __syncthreads();
#pragma unroll
        for (int k = 0; k < 16; k++) {
            float4 b = *reinterpret_cast<const float4*>(&Bs[k][tx * 4]);
            float a = As[w * ASTRIDE + k0 + k];
            acc[0] += a * b.x; acc[1] += a * b.y;
            acc[2] += a * b.z; acc[3] += a * b.w;
        }
        __syncthreads();
    }

    {
        float4 o;
        o.x = sigmoidf_stable(acc[0]);
        o.y = sigmoidf_stable(acc[1]);
        o.z = sigmoidf_stable(acc[2]);
        o.w = sigmoidf_stable(acc[3]);
        *reinterpret_cast<float4*>(&Hs[w * 132 + tx * 4]) = o;
    }
    __syncthreads();

    // ---- projection: z[8][64] = Hs[8][128] @ Wd[128][64] ----
    {
        int r  = t >> 5;
        int cg = t & 31;
        float s0 = 0.f, s1 = 0.f;
#pragma unroll
        for (int k = 0; k < 128; k++) {
            float hv = Hs[r * 132 + k];
            float2 wd = *reinterpret_cast<const float2*>(&Wd[k * DDIM + cg * 2]);
            s0 += hv * wd.x;
            s1 += hv * wd.y;
        }
        int R = blockIdx.x * 8 + r;
        int set = R >> 8, i = R & 255;
        float2 z = make_float2(s0, s1);
        *reinterpret_cast<float2*>(
            &out[((size_t)(set * 3 + head) * BATCH + i) * DDIM + cg * 2]) = z;
    }
}

// ---------------------------------------------------------------------------
// Host-side JAX threefry reproduction (partitionable mode)
// ---------------------------------------------------------------------------
namespace tfry {

static inline uint32_t rotl32(uint32_t x, int d) { return (x << d) | (x >> (32 - d)); }

struct Key { uint32_t a, b; };

static Key threefry2x32(Key k, uint32_t x0, uint32_t x1) {
    uint32_t ks0 = k.a, ks1 = k.b, ks2 = k.a ^ k.b ^ 0x1BD11BDAu;
    x0 += ks0; x1 += ks1;
    static const int R0[4] = {13, 15, 26, 6};
    static const int R1[4] = {17, 29, 16, 24};
    auto rounds4 = [&](const int* R) {
        for (int i = 0; i < 4; i++) { x0 += x1; x1 = rotl32(x1, R[i]); x1 ^= x0; }
    };
    rounds4(R0); x0 += ks1; x1 += ks2 + 1u;
    rounds4(R1); x0 += ks2; x1 += ks0 + 2u;
    rounds4(R0); x0 += ks0; x1 += ks1 + 3u;
    rounds4(R1); x0 += ks1; x1 += ks2 + 4u;
    rounds4(R0); x0 += ks2; x1 += ks0 + 5u;
    return Key{x0, x1};
}

static Key fold(Key k, uint32_t i) { return threefry2x32(k, 0u, i); }

static void perm64_prefix(Key key, int n, int* out) {
    Key subkey = fold(key, 1);
    uint32_t bits[64];
    int idx[64];
    for (int i = 0; i < 64; i++) {
        Key r = threefry2x32(subkey, 0u, (uint32_t)i);
        bits[i] = r.a ^ r.b;
        idx[i] = i;
    }
    std::stable_sort(idx, idx + 64,
                     [&](int x, int y) { return bits[x] < bits[y]; });
    for (int j = 0; j < n; j++) out[j] = idx[j];
}

}  // namespace tfry

// ---------------------------------------------------------------------------
// kernel_launch
// ---------------------------------------------------------------------------
extern "C" void kernel_launch(void* const* d_in, const int* in_sizes, int n_in,
                              void* d_out, int out_size) {
    const int*   nodes1  = (const int*)d_in[0];
    const int*   nodes2  = (const int*)d_in[1];
    const int*   nbr_out = (const int*)d_in[2];
    const int*   nbr_in  = (const int*)d_in[3];
    const float* feat    = (const float*)d_in[4];
    const float* W_in    = (const float*)d_in[5];
    const float* W_mean  = (const float*)d_in[6];
    const float* W_std   = (const float*)d_in[7];
    const float* W_pi    = (const float*)d_in[8];
    const float* Wd_mean = (const float*)d_in[11];
    const float* Wd_std  = (const float*)d_in[12];
    const float* Wd_pi   = (const float*)d_in[13];
    float* out = (float*)d_out;

    cudaFuncSetAttribute(fused_l0s1, cudaFuncAttributeMaxDynamicSharedMemorySize,
                         SMEM_FUSED);

    // --- host threefry: sampling column indices ---
    ColsAll cols;
    tfry::Key root{0u, 42u};
    tfry::Key kset[2] = {tfry::fold(root, 0), tfry::fold(root, 1)};
    for (int set = 0; set < 2; set++) {
        tfry::Key key = kset[set];
        {
            tfry::Key nk = tfry::fold(key, 0);
            tfry::Key p1 = tfry::fold(key, 1);
            tfry::Key p2 = tfry::fold(key, 2);
            tfry::perm64_prefix(p1, NN1, cols.out0[set]);
            tfry::perm64_prefix(p2, NN1, cols.in0[set]);
            key = nk;
        }
        {
            tfry::Key p1 = tfry::fold(key, 1);
            tfry::Key p2 = tfry::fold(key, 2);
            tfry::perm64_prefix(p1, NN0, cols.out1[set]);
            tfry::perm64_prefix(p2, NN0, cols.in1[set]);
        }
    }

    // --- pipeline: 4 launches ---
    comb_b1_prep<<<PREP_BLOCKS + B1_BLOCKS, 256>>>(nodes1, nodes2, nbr_out,
                                                   nbr_in, W_in, cols);        // #1
    build_lvl2<<<(2 * ROWS2 + 255) / 256, 256>>>(nbr_out, nbr_in, cols);       // #2
    fused_l0s1<<<L0_BLOCKS + S1_BLOCKS, 256, SMEM_FUSED>>>(feat, nodes1,
                                                           nodes2, W_in);      // #3
    fused_s2<<<dim3(64, 3), 256>>>(W_mean, W_std, W_pi,
                                   Wd_mean, Wd_std, Wd_pi, out);               // #4
}